// round 1
// baseline (speedup 1.0000x reference)
#include <cuda_runtime.h>
#include <math.h>

#define BSZ   8
#define TLEN  4096
#define EDIM  1024
#define HDIM  128
#define MTOT  (BSZ * TLEN)   // 32768

// Scratch for projected Q, K, V (16 MB each) — __device__ globals per harness rules.
__device__ float Qg[MTOT * HDIM];
__device__ float Kg[MTOT * HDIM];
__device__ float Vg[MTOT * HDIM];

// ---------------------------------------------------------------------------
// Kernel 1: projection GEMM.  O[M,128] = X[M,1024] @ W[1024,128]
// BM=128, BN=128 (full width), BK=16, 256 threads, 8x8 register tile.
// which: 0->Qg, 1->Kg, 2->Vg
// ---------------------------------------------------------------------------
__global__ __launch_bounds__(256) void proj_gemm(const float* __restrict__ X,
                                                 const float* __restrict__ W,
                                                 int which) {
    __shared__ float As[16 * 132];   // k-major, padded stride 132 (2-way max on store)
    __shared__ float Bs[16 * 128];

    float* O = (which == 0) ? Qg : (which == 1) ? Kg : Vg;

    const int m0  = blockIdx.x * 128;
    const int tid = threadIdx.x;
    const int tm  = tid >> 4;    // 0..15 -> rows tm*8..tm*8+7
    const int tn  = tid & 15;    // 0..15 -> cols tn*8..tn*8+7

    float acc[8][8];
#pragma unroll
    for (int i = 0; i < 8; i++)
#pragma unroll
        for (int j = 0; j < 8; j++) acc[i][j] = 0.f;

    for (int k0 = 0; k0 < EDIM; k0 += 16) {
        // Load X tile 128x16 -> As[k][m]
#pragma unroll
        for (int it = 0; it < 2; it++) {
            int idx = tid + it * 256;       // 0..511
            int r   = idx >> 2;             // 0..127
            int c4  = idx & 3;              // k-chunk
            float4 v = *(const float4*)(X + (size_t)(m0 + r) * EDIM + k0 + c4 * 4);
            As[(c4 * 4 + 0) * 132 + r] = v.x;
            As[(c4 * 4 + 1) * 132 + r] = v.y;
            As[(c4 * 4 + 2) * 132 + r] = v.z;
            As[(c4 * 4 + 3) * 132 + r] = v.w;
        }
        // Load W tile 16x128 -> Bs[k][n]
#pragma unroll
        for (int it = 0; it < 2; it++) {
            int idx = tid + it * 256;
            int kk  = idx >> 5;             // 0..15
            int n4  = idx & 31;
            *(float4*)(Bs + kk * 128 + n4 * 4) =
                *(const float4*)(W + (size_t)(k0 + kk) * HDIM + n4 * 4);
        }
        __syncthreads();

#pragma unroll
        for (int kk = 0; kk < 16; kk++) {
            float a[8], b[8];
            *(float4*)(a)     = *(const float4*)(As + kk * 132 + tm * 8);
            *(float4*)(a + 4) = *(const float4*)(As + kk * 132 + tm * 8 + 4);
            *(float4*)(b)     = *(const float4*)(Bs + kk * 128 + tn * 8);
            *(float4*)(b + 4) = *(const float4*)(Bs + kk * 128 + tn * 8 + 4);
#pragma unroll
            for (int i = 0; i < 8; i++)
#pragma unroll
                for (int j = 0; j < 8; j++) acc[i][j] += a[i] * b[j];
        }
        __syncthreads();
    }

#pragma unroll
    for (int i = 0; i < 8; i++) {
        float* orow = O + (size_t)(m0 + tm * 8 + i) * HDIM + tn * 8;
        *(float4*)(orow)     = make_float4(acc[i][0], acc[i][1], acc[i][2], acc[i][3]);
        *(float4*)(orow + 4) = make_float4(acc[i][4], acc[i][5], acc[i][6], acc[i][7]);
    }
}

// ---------------------------------------------------------------------------
// Kernel 2: causal flash attention.
// Block = (q-tile of 64 rows, batch). 256 threads as 16x16 (ty, tx).
// S tile: thread owns rows 4ty..+3, cols 4tx..+3.
// O tile: thread owns rows 4ty..+3, cols 8tx..+7.
// smem: Qs[64][132], Ks[64][129] (P aliases it), Vs[64][132]  -> 98.25 KB -> 2 blocks/SM
// ---------------------------------------------------------------------------
#define QS_STRIDE 132
#define KS_STRIDE 129
#define VS_STRIDE 132
#define PS_STRIDE 68
#define SMEM_FLOATS (64 * (QS_STRIDE + KS_STRIDE + VS_STRIDE))
#define SMEM_BYTES  (SMEM_FLOATS * 4)

__global__ __launch_bounds__(256, 2) void flash_kernel(float* __restrict__ Out) {
    extern __shared__ float sm[];
    float* Qs = sm;
    float* Ks = sm + 64 * QS_STRIDE;
    float* Vs = Ks + 64 * KS_STRIDE;
    float* Ps = Ks;   // alias: Ks dead after S-compute, reloaded next k-tile

    const int qt  = 63 - blockIdx.x;   // heavy tiles first
    const int b   = blockIdx.y;
    const int tid = threadIdx.x;
    const int ty  = tid >> 4;
    const int tx  = tid & 15;

    const size_t baseQ = ((size_t)b * TLEN + (size_t)qt * 64) * HDIM;

    // Load Q tile, pre-scaled by 1/sqrt(H)
    const float inv = 0.08838834764831845f;
#pragma unroll
    for (int it = 0; it < 8; it++) {
        int idx = tid + it * 256;          // 0..2047
        int r   = idx >> 5;                // 0..63
        int c4  = idx & 31;
        float4 v = *(const float4*)(Qg + baseQ + (size_t)r * HDIM + c4 * 4);
        v.x *= inv; v.y *= inv; v.z *= inv; v.w *= inv;
        *(float4*)(Qs + r * QS_STRIDE + c4 * 4) = v;
    }

    float o[4][8];
    float mrow[4], lrow[4];
#pragma unroll
    for (int i = 0; i < 4; i++) {
        mrow[i] = -1e30f;
        lrow[i] = 0.f;
#pragma unroll
        for (int c = 0; c < 8; c++) o[i][c] = 0.f;
    }

    const float4* qrow0 = (const float4*)(Qs + (4 * ty + 0) * QS_STRIDE);
    const float4* qrow1 = (const float4*)(Qs + (4 * ty + 1) * QS_STRIDE);
    const float4* qrow2 = (const float4*)(Qs + (4 * ty + 2) * QS_STRIDE);
    const float4* qrow3 = (const float4*)(Qs + (4 * ty + 3) * QS_STRIDE);
    const float* k0p = Ks + (4 * tx + 0) * KS_STRIDE;
    const float* k1p = Ks + (4 * tx + 1) * KS_STRIDE;
    const float* k2p = Ks + (4 * tx + 2) * KS_STRIDE;
    const float* k3p = Ks + (4 * tx + 3) * KS_STRIDE;

    for (int kt = 0; kt <= qt; kt++) {
        const size_t baseK = ((size_t)b * TLEN + (size_t)kt * 64) * HDIM;

        // Load K and V tiles
#pragma unroll
        for (int it = 0; it < 8; it++) {
            int idx = tid + it * 256;
            int r   = idx >> 5;
            int c4  = idx & 31;
            float4 kv = *(const float4*)(Kg + baseK + (size_t)r * HDIM + c4 * 4);
            Ks[r * KS_STRIDE + c4 * 4 + 0] = kv.x;
            Ks[r * KS_STRIDE + c4 * 4 + 1] = kv.y;
            Ks[r * KS_STRIDE + c4 * 4 + 2] = kv.z;
            Ks[r * KS_STRIDE + c4 * 4 + 3] = kv.w;
            float4 vv = *(const float4*)(Vg + baseK + (size_t)r * HDIM + c4 * 4);
            *(float4*)(Vs + r * VS_STRIDE + c4 * 4) = vv;
        }
        __syncthreads();

        // S = Q K^T  (64x64, 4x4 per thread)
        float s[4][4];
#pragma unroll
        for (int i = 0; i < 4; i++)
#pragma unroll
            for (int j = 0; j < 4; j++) s[i][j] = 0.f;

        for (int h4 = 0; h4 < 32; h4++) {
            float qa[4][4];
            *(float4*)qa[0] = qrow0[h4];
            *(float4*)qa[1] = qrow1[h4];
            *(float4*)qa[2] = qrow2[h4];
            *(float4*)qa[3] = qrow3[h4];
#pragma unroll
            for (int e = 0; e < 4; e++) {
                float kb0 = k0p[h4 * 4 + e];
                float kb1 = k1p[h4 * 4 + e];
                float kb2 = k2p[h4 * 4 + e];
                float kb3 = k3p[h4 * 4 + e];
#pragma unroll
                for (int i = 0; i < 4; i++) {
                    s[i][0] += qa[i][e] * kb0;
                    s[i][1] += qa[i][e] * kb1;
                    s[i][2] += qa[i][e] * kb2;
                    s[i][3] += qa[i][e] * kb3;
                }
            }
        }

        // Causal mask on the diagonal tile (same local offsets -> local compare)
        if (kt == qt) {
#pragma unroll
            for (int i = 0; i < 4; i++)
#pragma unroll
                for (int j = 0; j < 4; j++)
                    if (4 * tx + j > 4 * ty + i) s[i][j] = -1e30f;
        }

        // Online softmax (row stats replicated across the 16 tx lanes of each row)
#pragma unroll
        for (int i = 0; i < 4; i++) {
            float mt = fmaxf(fmaxf(s[i][0], s[i][1]), fmaxf(s[i][2], s[i][3]));
            mt = fmaxf(mt, __shfl_xor_sync(0xffffffffu, mt, 8));
            mt = fmaxf(mt, __shfl_xor_sync(0xffffffffu, mt, 4));
            mt = fmaxf(mt, __shfl_xor_sync(0xffffffffu, mt, 2));
            mt = fmaxf(mt, __shfl_xor_sync(0xffffffffu, mt, 1));
            float mnew  = fmaxf(mrow[i], mt);
            float alpha = __expf(mrow[i] - mnew);
            mrow[i] = mnew;
            float rs = 0.f;
#pragma unroll
            for (int j = 0; j < 4; j++) {
                s[i][j] = __expf(s[i][j] - mnew);
                rs += s[i][j];
            }
            rs += __shfl_xor_sync(0xffffffffu, rs, 8);
            rs += __shfl_xor_sync(0xffffffffu, rs, 4);
            rs += __shfl_xor_sync(0xffffffffu, rs, 2);
            rs += __shfl_xor_sync(0xffffffffu, rs, 1);
            lrow[i] = lrow[i] * alpha + rs;
#pragma unroll
            for (int c = 0; c < 8; c++) o[i][c] *= alpha;
        }

        __syncthreads();   // all S-reads of Ks done before P overwrites it

        // Stage P to smem (aliases Ks region, stride 68)
#pragma unroll
        for (int i = 0; i < 4; i++)
            *(float4*)(Ps + (4 * ty + i) * PS_STRIDE + 4 * tx) =
                make_float4(s[i][0], s[i][1], s[i][2], s[i][3]);
        __syncthreads();

        // O += P V  (64x128)
        for (int j = 0; j < 64; j++) {
            float p0 = Ps[(4 * ty + 0) * PS_STRIDE + j];
            float p1 = Ps[(4 * ty + 1) * PS_STRIDE + j];
            float p2 = Ps[(4 * ty + 2) * PS_STRIDE + j];
            float p3 = Ps[(4 * ty + 3) * PS_STRIDE + j];
            float va[8];
            *(float4*)(va)     = *(const float4*)(Vs + j * VS_STRIDE + 8 * tx);
            *(float4*)(va + 4) = *(const float4*)(Vs + j * VS_STRIDE + 8 * tx + 4);
#pragma unroll
            for (int c = 0; c < 8; c++) {
                o[0][c] += p0 * va[c];
                o[1][c] += p1 * va[c];
                o[2][c] += p2 * va[c];
                o[3][c] += p3 * va[c];
            }
        }
        __syncthreads();   // PV done before next tile overwrites Ks/Vs
    }

    // Epilogue: normalize and store
#pragma unroll
    for (int i = 0; i < 4; i++) {
        float rl = 1.f / lrow[i];
        float* orow = Out + baseQ + (size_t)(4 * ty + i) * HDIM + 8 * tx;
        *(float4*)(orow)     = make_float4(o[i][0] * rl, o[i][1] * rl, o[i][2] * rl, o[i][3] * rl);
        *(float4*)(orow + 4) = make_float4(o[i][4] * rl, o[i][5] * rl, o[i][6] * rl, o[i][7] * rl);
    }
}

// ---------------------------------------------------------------------------
extern "C" void kernel_launch(void* const* d_in, const int* in_sizes, int n_in,
                              void* d_out, int out_size) {
    const float* x  = (const float*)d_in[0];
    const float* Wq = (const float*)d_in[1];
    const float* Wk = (const float*)d_in[2];
    const float* Wv = (const float*)d_in[3];
    float* out = (float*)d_out;

    (void)in_sizes; (void)n_in; (void)out_size;

    // QKV projections (write to __device__ scratch)
    proj_gemm<<<MTOT / 128, 256>>>(x, Wq, 0);
    proj_gemm<<<MTOT / 128, 256>>>(x, Wk, 1);
    proj_gemm<<<MTOT / 128, 256>>>(x, Wv, 2);

    // Flash attention — needs >48KB dynamic smem (idempotent, capture-safe)
    cudaFuncSetAttribute(flash_kernel, cudaFuncAttributeMaxDynamicSharedMemorySize,
                         SMEM_BYTES);
    flash_kernel<<<dim3(64, BSZ), 256, SMEM_BYTES>>>(out);
}

// round 2
// speedup vs baseline: 1.1643x; 1.1643x over previous
#include <cuda_runtime.h>
#include <math.h>

#define BSZ   8
#define TLEN  4096
#define EDIM  1024
#define HDIM  128
#define MTOT  (BSZ * TLEN)   // 32768

// Scratch: Q,V row-major [B*T][H]; K transposed [B][H][T].
__device__ float Qg [MTOT * HDIM];
__device__ float Ktg[MTOT * HDIM];
__device__ float Vg [MTOT * HDIM];

// ---------------------------------------------------------------------------
// Kernel 1: projection GEMM.  O[M,128] = X[M,1024] @ W[1024,128]
// BM=128, BN=128, BK=16, 256 threads, 8x8 register tile.
// which: 0 -> Qg (row-major), 1 -> Ktg (transposed [B][H][T]), 2 -> Vg.
// ---------------------------------------------------------------------------
__global__ __launch_bounds__(256) void proj_gemm(const float* __restrict__ X,
                                                 const float* __restrict__ W,
                                                 int which) {
    __shared__ float As[16 * 132];
    __shared__ float Bs[16 * 128];

    const int m0  = blockIdx.x * 128;
    const int tid = threadIdx.x;
    const int tm  = tid >> 4;
    const int tn  = tid & 15;

    float acc[8][8];
#pragma unroll
    for (int i = 0; i < 8; i++)
#pragma unroll
        for (int j = 0; j < 8; j++) acc[i][j] = 0.f;

    for (int k0 = 0; k0 < EDIM; k0 += 16) {
#pragma unroll
        for (int it = 0; it < 2; it++) {
            int idx = tid + it * 256;
            int r   = idx >> 2;
            int c4  = idx & 3;
            float4 v = *(const float4*)(X + (size_t)(m0 + r) * EDIM + k0 + c4 * 4);
            As[(c4 * 4 + 0) * 132 + r] = v.x;
            As[(c4 * 4 + 1) * 132 + r] = v.y;
            As[(c4 * 4 + 2) * 132 + r] = v.z;
            As[(c4 * 4 + 3) * 132 + r] = v.w;
        }
#pragma unroll
        for (int it = 0; it < 2; it++) {
            int idx = tid + it * 256;
            int kk  = idx >> 5;
            int n4  = idx & 31;
            *(float4*)(Bs + kk * 128 + n4 * 4) =
                *(const float4*)(W + (size_t)(k0 + kk) * HDIM + n4 * 4);
        }
        __syncthreads();

#pragma unroll
        for (int kk = 0; kk < 16; kk++) {
            float a[8], b[8];
            *(float4*)(a)     = *(const float4*)(As + kk * 132 + tm * 8);
            *(float4*)(a + 4) = *(const float4*)(As + kk * 132 + tm * 8 + 4);
            *(float4*)(b)     = *(const float4*)(Bs + kk * 128 + tn * 8);
            *(float4*)(b + 4) = *(const float4*)(Bs + kk * 128 + tn * 8 + 4);
#pragma unroll
            for (int i = 0; i < 8; i++)
#pragma unroll
                for (int j = 0; j < 8; j++) acc[i][j] += a[i] * b[j];
        }
        __syncthreads();
    }

    if (which == 1) {
        // K: store transposed into Ktg[b][h][t]
        const int b  = m0 >> 12;                 // 4096 tokens per batch
        const int t0 = (m0 & 4095) + tm * 8;
        float* kb = Ktg + (size_t)b * HDIM * TLEN;
#pragma unroll
        for (int j = 0; j < 8; j++) {
            float* col = kb + (size_t)(tn * 8 + j) * TLEN + t0;
#pragma unroll
            for (int i = 0; i < 8; i++) col[i] = acc[i][j];
        }
    } else {
        float* O = (which == 0) ? Qg : Vg;
#pragma unroll
        for (int i = 0; i < 8; i++) {
            float* orow = O + (size_t)(m0 + tm * 8 + i) * HDIM + tn * 8;
            *(float4*)(orow)     = make_float4(acc[i][0], acc[i][1], acc[i][2], acc[i][3]);
            *(float4*)(orow + 4) = make_float4(acc[i][4], acc[i][5], acc[i][6], acc[i][7]);
        }
    }
}

// ---------------------------------------------------------------------------
// Kernel 2: causal flash attention, BQ=128, BK=128, 256 threads (16x16),
// 8x8 register tiles for both S and O.
// smem: Qs[128][132] + Kt[128][132] (h-major, aliased by P) + Vs[128][132]
//     = 202.75 KB -> 1 block/SM.
// ---------------------------------------------------------------------------
#define QS_ST 132
#define KT_ST 132
#define VS_ST 132
#define PS_ST 132
#define TILE_FLOATS (128 * 132)
#define SMEM_BYTES  (3 * TILE_FLOATS * 4)

__global__ __launch_bounds__(256, 1) void flash_kernel(float* __restrict__ Out) {
    extern __shared__ float sm[];
    float* Qs = sm;
    float* Kt = sm + TILE_FLOATS;
    float* Vs = sm + 2 * TILE_FLOATS;
    float* Ps = Kt;   // alias: Kt dead after S-compute

    const int qt  = 31 - blockIdx.x;   // heavy q-tiles first
    const int b   = blockIdx.y;
    const int tid = threadIdx.x;
    const int ty  = tid >> 4;
    const int tx  = tid & 15;

    const size_t baseQ  = ((size_t)b * TLEN + (size_t)qt * 128) * HDIM;
    const float* ktbase = Ktg + (size_t)b * HDIM * TLEN;

    // Load Q tile (row-major, pre-scaled by 1/sqrt(H))
    const float inv = 0.08838834764831845f;
#pragma unroll
    for (int it = 0; it < 16; it++) {
        int idx = tid + it * 256;          // 0..4095
        int r   = idx >> 5;                // 0..127
        int c4  = idx & 31;
        float4 v = *(const float4*)(Qg + baseQ + (size_t)r * HDIM + c4 * 4);
        v.x *= inv; v.y *= inv; v.z *= inv; v.w *= inv;
        *(float4*)(Qs + r * QS_ST + c4 * 4) = v;
    }

    float o[8][8];
    float mr[8], lr[8];
#pragma unroll
    for (int i = 0; i < 8; i++) {
        mr[i] = -1e30f;
        lr[i] = 0.f;
#pragma unroll
        for (int c = 0; c < 8; c++) o[i][c] = 0.f;
    }

    const float* qb = Qs + (8 * ty) * QS_ST;

    for (int kt = 0; kt <= qt; kt++) {
        // Load K tile (h-major from Ktg: coalesced gmem, dense smem stores)
        const float* ksrc = ktbase + (size_t)kt * 128;
#pragma unroll
        for (int it = 0; it < 16; it++) {
            int idx = tid + it * 256;
            int h   = idx >> 5;            // 0..127
            int c4  = idx & 31;
            float4 v = *(const float4*)(ksrc + (size_t)h * TLEN + c4 * 4);
            *(float4*)(Kt + h * KT_ST + c4 * 4) = v;
        }
        // Load V tile (row-major)
        const size_t baseV = ((size_t)b * TLEN + (size_t)kt * 128) * HDIM;
#pragma unroll
        for (int it = 0; it < 16; it++) {
            int idx = tid + it * 256;
            int r   = idx >> 5;
            int c4  = idx & 31;
            *(float4*)(Vs + r * VS_ST + c4 * 4) =
                *(const float4*)(Vg + baseV + (size_t)r * HDIM + c4 * 4);
        }
        __syncthreads();

        // ---- S = Q K^T : 8x8 per thread, rows 8ty.., cols 8tx.. ----
        float s[8][8];
#pragma unroll
        for (int i = 0; i < 8; i++)
#pragma unroll
            for (int j = 0; j < 8; j++) s[i][j] = 0.f;

#pragma unroll 2
        for (int h4 = 0; h4 < 32; h4++) {
            float qa[8][4];
#pragma unroll
            for (int i = 0; i < 8; i++)
                *(float4*)qa[i] = *(const float4*)(qb + i * QS_ST + 4 * h4);
#pragma unroll
            for (int e = 0; e < 4; e++) {
                float kb[8];
                const float* kr = Kt + (4 * h4 + e) * KT_ST + 8 * tx;
                *(float4*)(kb)     = *(const float4*)(kr);
                *(float4*)(kb + 4) = *(const float4*)(kr + 4);
#pragma unroll
                for (int i = 0; i < 8; i++)
#pragma unroll
                    for (int j = 0; j < 8; j++) s[i][j] += qa[i][e] * kb[j];
            }
        }

        // Causal mask on the diagonal tile
        if (kt == qt) {
#pragma unroll
            for (int i = 0; i < 8; i++)
#pragma unroll
                for (int j = 0; j < 8; j++)
                    if (8 * tx + j > 8 * ty + i) s[i][j] = -1e30f;
        }

        // ---- online softmax (row stats across the 16 tx lanes) ----
#pragma unroll
        for (int i = 0; i < 8; i++) {
            float mt = s[i][0];
#pragma unroll
            for (int j = 1; j < 8; j++) mt = fmaxf(mt, s[i][j]);
            mt = fmaxf(mt, __shfl_xor_sync(0xffffffffu, mt, 8));
            mt = fmaxf(mt, __shfl_xor_sync(0xffffffffu, mt, 4));
            mt = fmaxf(mt, __shfl_xor_sync(0xffffffffu, mt, 2));
            mt = fmaxf(mt, __shfl_xor_sync(0xffffffffu, mt, 1));
            float mnew  = fmaxf(mr[i], mt);
            float alpha = __expf(mr[i] - mnew);
            mr[i] = mnew;
            float rs = 0.f;
#pragma unroll
            for (int j = 0; j < 8; j++) {
                s[i][j] = __expf(s[i][j] - mnew);
                rs += s[i][j];
            }
            rs += __shfl_xor_sync(0xffffffffu, rs, 8);
            rs += __shfl_xor_sync(0xffffffffu, rs, 4);
            rs += __shfl_xor_sync(0xffffffffu, rs, 2);
            rs += __shfl_xor_sync(0xffffffffu, rs, 1);
            lr[i] = lr[i] * alpha + rs;
#pragma unroll
            for (int c = 0; c < 8; c++) o[i][c] *= alpha;
        }

        __syncthreads();   // all Kt reads done before P overwrites it

        // Stage P (aliases Kt)
#pragma unroll
        for (int i = 0; i < 8; i++) {
            float* pr = Ps + (8 * ty + i) * PS_ST + 8 * tx;
            *(float4*)(pr)     = make_float4(s[i][0], s[i][1], s[i][2], s[i][3]);
            *(float4*)(pr + 4) = make_float4(s[i][4], s[i][5], s[i][6], s[i][7]);
        }
        __syncthreads();

        // ---- O += P V : 8x8 per thread, rows 8ty.., h-cols 8tx.. ----
#pragma unroll 2
        for (int j4 = 0; j4 < 32; j4++) {
            float pa[8][4];
#pragma unroll
            for (int i = 0; i < 8; i++)
                *(float4*)pa[i] = *(const float4*)(Ps + (8 * ty + i) * PS_ST + 4 * j4);
#pragma unroll
            for (int e = 0; e < 4; e++) {
                float va[8];
                const float* vr = Vs + (4 * j4 + e) * VS_ST + 8 * tx;
                *(float4*)(va)     = *(const float4*)(vr);
                *(float4*)(va + 4) = *(const float4*)(vr + 4);
#pragma unroll
                for (int i = 0; i < 8; i++)
#pragma unroll
                    for (int c = 0; c < 8; c++) o[i][c] += pa[i][e] * va[c];
            }
        }
        __syncthreads();   // PV done before next tile overwrites Kt/Vs
    }

    // Epilogue
#pragma unroll
    for (int i = 0; i < 8; i++) {
        float rl = 1.f / lr[i];
        float* orow = Out + baseQ + (size_t)(8 * ty + i) * HDIM + 8 * tx;
        *(float4*)(orow)     = make_float4(o[i][0] * rl, o[i][1] * rl, o[i][2] * rl, o[i][3] * rl);
        *(float4*)(orow + 4) = make_float4(o[i][4] * rl, o[i][5] * rl, o[i][6] * rl, o[i][7] * rl);
    }
}

// ---------------------------------------------------------------------------
extern "C" void kernel_launch(void* const* d_in, const int* in_sizes, int n_in,
                              void* d_out, int out_size) {
    const float* x  = (const float*)d_in[0];
    const float* Wq = (const float*)d_in[1];
    const float* Wk = (const float*)d_in[2];
    const float* Wv = (const float*)d_in[3];
    float* out = (float*)d_out;

    (void)in_sizes; (void)n_in; (void)out_size;

    proj_gemm<<<MTOT / 128, 256>>>(x, Wq, 0);
    proj_gemm<<<MTOT / 128, 256>>>(x, Wk, 1);
    proj_gemm<<<MTOT / 128, 256>>>(x, Wv, 2);

    cudaFuncSetAttribute(flash_kernel, cudaFuncAttributeMaxDynamicSharedMemorySize,
                         SMEM_BYTES);
    flash_kernel<<<dim3(32, BSZ), 256, SMEM_BYTES>>>(out);
}